// round 2
// baseline (speedup 1.0000x reference)
#include <cuda_runtime.h>

#define Nn 768
#define Hh 32
#define Ee 24576
#define Pp 4096
#define NCH 8
#define CW 96
#define NBLK 96
#define NBT (NBLK*256)

// ---------------- scratch (__device__ globals: allocation-free) ----------------
__device__ unsigned char d_adj [Nn*Nn];
__device__ unsigned char d_need[Nn*Nn];          // (i,j) required by pos
__device__ unsigned char d_maskb[Nn*Nn];
__device__ float d_dinv[Nn];
__device__ float d_h [Nn*Hh];
__device__ float d_hT[Nn*Hh];
__device__ int   d_cnt2[Nn*NCH];
__device__ int   d_base[Nn*NCH+1];
__device__ int   d_fill[Nn*NCH];
__device__ int   d_col[Ee];
__device__ int   d_cu [Ee];
__device__ float d_xe [Ee*Hh];
__device__ float d_mul[Ee*Hh];
__device__ float d_z  [(size_t)Nn*Nn*Hh];        // written only at need entries
__device__ float d_p1[NBLK*Hh], d_p2[NBLK*Hh];   // per-block norm partials
__device__ float d_S1[Hh], d_S2[Hh];
__device__ int   d_cntM;
__device__ int   d_barcnt;                        // reset by k_rowC each run

// ---------------- soft grid barrier (96 resident blocks) ----------------
__device__ __forceinline__ void gbar(int phase) {
    __threadfence();                 // publish my writes (gpu scope)
    __syncthreads();
    if (threadIdx.x == 0) {
        atomicAdd(&d_barcnt, 1);
        int target = phase * NBLK;
        while (*(volatile int*)&d_barcnt < target) __nanosleep(32);
        __threadfence();             // CCTL.IVALL: invalidate stale L1 lines
    }
    __syncthreads();
}

// ---------------- mega-kernel: setup + GCN + edge MLPs ----------------
__global__ void __launch_bounds__(256) k_mega(
    const int* __restrict__ x, const int* __restrict__ ei, const int* __restrict__ pos,
    const float* __restrict__ emb, const float* __restrict__ gcnW, const float* __restrict__ gcnb,
    const float* __restrict__ W1, const float* __restrict__ b1,
    const float* __restrict__ W2, const float* __restrict__ b2)
{
    __shared__ float red1[8][32], red2[8][32];
    __shared__ float sMean[32], sInv[32];
    __shared__ int stot[257];

    int tid = threadIdx.x, w = tid>>5, lane = tid&31;
    int bid = blockIdx.x;
    int gtid = bid*256 + tid;
    int gw = bid*8 + w;              // 0..767 : one row per warp

    // ---- P0: zero scratch + embed ----
    {
        int4 z4 = make_int4(0,0,0,0);
        for (int t=gtid; t<Nn*Nn/16; t+=NBT){ ((int4*)d_adj)[t]=z4; ((int4*)d_need)[t]=z4; }
        for (int t=gtid; t<Nn*NCH; t+=NBT) d_cnt2[t]=0;
        if (gtid < Hh){ d_S1[gtid]=0.f; d_S2[gtid]=0.f; }
        if (gtid == 0) d_cntM = 0;
        d_h[gw*Hh+lane] = emb[x[gw]*Hh+lane];
    }
    gbar(1);

    // ---- P1: scatter adjacency + counts + need map ----
    { int e=gtid; if (e<Ee){ int u=ei[e], v=ei[Ee+e]; d_adj[u*Nn+v]=1; atomicAdd(&d_cnt2[u*NCH+v/CW],1);} }
    { int p=gtid; if (p<Pp){ int a=pos[2*p], b=pos[2*p+1]; d_need[a*Nn+b]=1; d_need[b*Nn+a]=1; } }
    gbar(2);

    // ---- P2: dinv (all blocks) + chunk scan (block 0) ----
    {
        const int* rowi = (const int*)(d_adj + gw*Nn);
        int s = 0;
        #pragma unroll
        for (int t=0;t<6;t++){ int xw = rowi[t*32+lane]; s = __dp4a(xw, 0x01010101, s); }
        for (int o=16;o;o>>=1) s += __shfl_down_sync(0xffffffffu, s, o);
        if (lane==0) d_dinv[gw] = rsqrtf((float)s + 1.0f);
        if (bid == 0) {
            int lo = tid*24; int vals[24]; int run = 0;
            #pragma unroll
            for (int q=0;q<24;q++){ vals[q]=run; run += d_cnt2[lo+q]; }
            stot[tid] = run; __syncthreads();
            if (tid==0){ int r=0; for (int t=0;t<256;t++){ int xx=stot[t]; stot[t]=r; r+=xx; } stot[256]=r; }
            __syncthreads();
            int base = stot[tid];
            #pragma unroll
            for (int q=0;q<24;q++){ int vv = base+vals[q]; d_base[lo+q]=vv; d_fill[lo+q]=vv; }
            if (tid==0) d_base[Nn*NCH] = stot[256];
        }
    }
    gbar(3);

    // ---- P3: fill chunk-bucketed CSR ----
    { int e=gtid; if (e<Ee){ int u=ei[e], v=ei[Ee+e];
        int s = atomicAdd(&d_fill[u*NCH+v/CW],1); d_col[s]=v; d_cu[s]=u; } }
    gbar(4);

    // ---- GCN: 2 layers ----
    float hval = d_h[gw*Hh+lane];
    int ph = 4;
    #pragma unroll 1
    for (int l=0; l<2; l++) {
        // hW: hT = dinv * (h @ W_l)   (row-local)
        const float* W = gcnW + l*Hh*Hh;
        float acc = 0.f;
        #pragma unroll
        for (int k=0;k<32;k++) acc += __shfl_sync(0xffffffffu, hval, k) * W[k*Hh+lane];
        float dv = d_dinv[gw];
        d_hT[gw*Hh+lane] = dv*acc;
        gbar(++ph);

        // agg: v = dinv*(sum_adj hT + hT_self) + b
        const unsigned char* row = d_adj + gw*Nn;
        float aggv = 0.f;
        for (int jb=0; jb<Nn; jb+=32) {
            unsigned m = __ballot_sync(0xffffffffu, row[jb+lane]!=0);
            while (m){ int b = __ffs(m)-1; m &= m-1; aggv += d_hT[(jb+b)*Hh+lane]; }
        }
        float v = dv*(aggv + d_hT[gw*Hh+lane]) + gcnb[l*Hh+lane];

        // block-partial norm stats
        red1[w][lane]=v; red2[w][lane]=v*v;
        __syncthreads();
        if (w==0){
            float s1=0.f, s2=0.f;
            #pragma unroll
            for (int r=0;r<8;r++){ s1+=red1[r][lane]; s2+=red2[r][lane]; }
            d_p1[bid*32+lane]=s1; d_p2[bid*32+lane]=s2;
        }
        gbar(++ph);

        // global stats (each block independently) + normalize own row
        if (w==0){
            float s1=0.f, s2=0.f;
            for (int b=0;b<NBLK;b++){ s1+=d_p1[b*32+lane]; s2+=d_p2[b*32+lane]; }
            float mean = s1/(float)Nn;
            sMean[lane]=mean; sInv[lane]=rsqrtf(s2/(float)Nn - mean*mean + 1e-5f);
        }
        __syncthreads();
        hval = fmaxf((v - sMean[lane])*sInv[lane], 0.f);
        d_h[gw*Hh+lane] = hval;
        __syncthreads();
    }
    gbar(++ph);   // d_h final, CSR ready

    // ---- P9: edge MLPs (W-outer, 8 edges/warp in registers) ----
    {
        int s0 = gw*32;
        #pragma unroll 1
        for (int g=0; g<4; g++) {
            int sb = s0 + g*8;
            float hu[8], hv[8], x1[8], x2[8];
            #pragma unroll
            for (int e=0;e<8;e++){
                int u = d_cu[sb+e], v = d_col[sb+e];
                hu[e]=d_h[u*Hh+lane]; hv[e]=d_h[v*Hh+lane];
                x1[e]=b1[lane]; x2[e]=b2[lane];
            }
            #pragma unroll 4
            for (int k=0;k<32;k++){
                float w1a=W1[k*Hh+lane], w1b=W1[(k+32)*Hh+lane];
                float w2a=W2[k*Hh+lane], w2b=W2[(k+32)*Hh+lane];
                #pragma unroll
                for (int e=0;e<8;e++){
                    float a=__shfl_sync(0xffffffffu,hu[e],k);
                    float b=__shfl_sync(0xffffffffu,hv[e],k);
                    x1[e] += a*w1a + b*w1b;
                    x2[e] += a*w2a + b*w2b;
                }
            }
            #pragma unroll
            for (int e=0;e<8;e++){
                d_xe [(sb+e)*Hh+lane]=fmaxf(x1[e],0.f);
                d_mul[(sb+e)*Hh+lane]=fmaxf(x2[e],0.f);
            }
        }
    }
}

// ---------------- hot kernel: per-row 2-hop C + z + masked moments ----------------
__global__ void __launch_bounds__(256,2) k_rowC(const float* __restrict__ W3,
                                                const float* __restrict__ b3v) {
    extern __shared__ float Cs[];                           // Nn*Hh floats
    unsigned char* touched = (unsigned char*)(Cs + Nn*Hh);  // Nn bytes
    __shared__ float sr1[8][32], sr2[8][32];
    __shared__ int src[8];
    int tid = threadIdx.x, w = tid>>5, lane = tid&31;
    int i = blockIdx.x;

    if (i==0 && tid==0) d_barcnt = 0;   // reset mega-kernel barrier for next replay

    float4 z4 = make_float4(0.f,0.f,0.f,0.f);
    for (int t=tid; t<Nn*Hh/4; t+=256) ((float4*)Cs)[t]=z4;
    for (int t=tid; t<Nn; t+=256) touched[t]=0;
    __syncthreads();

    // phase 2: sparse 2-hop accumulation, warp w owns j-chunk [96w,96w+96)
    int es = d_base[i*NCH], ee = d_base[(i+1)*NCH];
    for (int e=es; e<ee; e++){
        int k = d_col[e];
        float xv = d_xe[e*Hh+lane];
        int f = d_base[k*NCH+w], fe = d_base[k*NCH+w+1];
        if (f < fe) {
            int j = d_col[f];
            float mv = d_mul[f*Hh+lane];
            while (++f < fe) {                       // software pipeline
                int jn = d_col[f];
                float mn = d_mul[f*Hh+lane];
                Cs[j*Hh+lane] += xv*mv;
                if (lane==0) touched[j]=1;
                j=jn; mv=mn;
            }
            Cs[j*Hh+lane] += xv*mv;
            if (lane==0) touched[j]=1;
        }
    }
    __syncthreads();

    // phase 3: z = C@W3 + af*W3[32] + b3; moments; store only needed entries
    float w3r[33];
    #pragma unroll
    for (int k=0;k<33;k++) w3r[k]=W3[k*Hh+lane];
    float bb = b3v[lane];
    float s1=0.f, s2=0.f; int c0=0;
    const size_t zrow = (size_t)i*Nn;
    #pragma unroll 1
    for (int t=0;t<3;t++){
        int j0 = w*CW + t*32;
        int j  = j0 + lane;
        unsigned mA = __ballot_sync(0xffffffffu, d_adj [i*Nn+j]!=0);
        unsigned mM = mA | __ballot_sync(0xffffffffu, touched[j]!=0);
        unsigned mN = __ballot_sync(0xffffffffu, d_need[i*Nn+j]!=0) & mM;
        d_maskb[i*Nn+j] = (unsigned char)((mM>>lane)&1u);
        c0 += __popc(mM);
        unsigned rem = mM;
        while (rem){
            int b = __ffs(rem)-1; rem &= rem-1;
            int jj = j0 + b;
            float acc = bb + (((mA>>b)&1u) ? w3r[32] : 0.f);
            const float4* Cj = (const float4*)(Cs + jj*Hh);
            #pragma unroll
            for (int k4=0;k4<8;k4++){
                float4 c = Cj[k4];
                acc += c.x*w3r[4*k4] + c.y*w3r[4*k4+1] + c.z*w3r[4*k4+2] + c.w*w3r[4*k4+3];
            }
            s1 += acc; s2 += acc*acc;
            if ((mN>>b)&1u) d_z[(zrow+jj)*Hh+lane] = acc;
        }
    }
    sr1[w][lane]=s1; sr2[w][lane]=s2; if (lane==0) src[w]=c0;
    __syncthreads();
    if (w==0){
        float a=0.f, b=0.f;
        #pragma unroll
        for (int r=0;r<8;r++){ a+=sr1[r][lane]; b+=sr2[r][lane]; }
        atomicAdd(&d_S1[lane], a);
        atomicAdd(&d_S2[lane], b);
        if (lane==0){ int cc=0; for (int r=0;r<8;r++) cc+=src[r]; atomicAdd(&d_cntM, cc); }
    }
}

// ---------------- output: stats finalize inline + pos gather ----------------
__global__ void k_pos(const int* __restrict__ pos, const float* __restrict__ linW,
                      const float* __restrict__ linb, float* __restrict__ out) {
    int w = threadIdx.x>>5, lane = threadIdx.x&31;
    int p = blockIdx.x*8 + w;
    float cnt = (float)d_cntM;
    float mean = d_S1[lane]/cnt;
    float inv  = rsqrtf(d_S2[lane]/cnt - mean*mean + 1e-5f);
    int p0 = pos[2*p], p1 = pos[2*p+1];
    float acc = d_h[p0*Hh+lane]*d_h[p1*Hh+lane]*linW[Hh+lane];
    if (d_maskb[p0*Nn+p1]) {
        float z1 = d_z[((size_t)p0*Nn+p1)*Hh+lane];
        float z2 = d_z[((size_t)p1*Nn+p0)*Hh+lane];
        acc += fmaxf((z1-mean)*inv,0.f)*fmaxf((z2-mean)*inv,0.f)*linW[lane];
    }
    for (int o=16;o;o>>=1) acc += __shfl_down_sync(0xffffffffu, acc, o);
    if (lane==0) out[p] = acc + linb[0];
}

// ---------------- launch ----------------
extern "C" void kernel_launch(void* const* d_in, const int* in_sizes, int n_in,
                              void* d_out, int out_size) {
    const int*   x    = (const int*)  d_in[0];
    const int*   ei   = (const int*)  d_in[1];
    const int*   pos  = (const int*)  d_in[2];
    const float* emb  = (const float*)d_in[3];
    const float* gcnW = (const float*)d_in[4];
    const float* gcnb = (const float*)d_in[5];
    const float* W1   = (const float*)d_in[6];
    const float* b1   = (const float*)d_in[7];
    const float* W2   = (const float*)d_in[8];
    const float* b2   = (const float*)d_in[9];
    const float* W3   = (const float*)d_in[10];
    const float* b3   = (const float*)d_in[11];
    const float* linW = (const float*)d_in[12];
    const float* linb = (const float*)d_in[13];
    float* out = (float*)d_out;

    const int smemC = Nn*Hh*(int)sizeof(float) + Nn + 128;   // ~99.2 KB dynamic
    cudaFuncSetAttribute(k_rowC, cudaFuncAttributeMaxDynamicSharedMemorySize, smemC);

    k_mega<<<NBLK,256>>>(x, ei, pos, emb, gcnW, gcnb, W1, b1, W2, b2);
    k_rowC<<<Nn,256,smemC>>>(W3, b3);
    k_pos <<<Pp/8,256>>>(pos, linW, linb, out);
}